// round 12
// baseline (speedup 1.0000x reference)
#include <cuda_runtime.h>
#include <cstdint>

// Problem constants (fixed by the reference).
#define ROWS       8192
#define COLS       8192
#define NUMEL      (1ULL * ROWS * COLS)          // 64M output floats
#define NCODES     (NUMEL / 4)                   // 16M codes (centroid_len = 4)
#define CB_ENTRIES 512                           // 2 codebooks * 256 centroids (float4)

#define BLOCK      256
#define CPT        4                               // codes per thread per tile
#define TILE_CODES (BLOCK * CPT)                   // 1024 codes
#define CODE_BYTES (TILE_CODES * 4)                // 4 KB codes per tile
#define SCALE_CNT  (TILE_CODES / 16)               // 64 scales per tile
#define SCALE_BYTES (SCALE_CNT * 4)                // 256 B
#define TILE_BYTES (TILE_CODES * 16)               // 16 KB output per tile
#define NTILES     ((int)(NCODES / TILE_CODES))    // 16384 (exact)
#define DEPTH      2
#define GRID       (152 * 4)                       // 608 blocks (49KB smem -> 4/SM)

// Fully async dequant pipeline:
//   in : cp.async.bulk GMEM->SMEM for codes+scales (mbarrier, depth 2)
//   out: cp.async.bulk SMEM->GMEM for 16KB output tiles (bulk_group, depth 2)
// Warps touch only shared memory; both global directions run on the bulk
// engines, so no warp ever blocks on a global-memory scoreboard.

__device__ __forceinline__ uint32_t smem_u32(const void* p) {
    uint32_t a;
    asm("{ .reg .u64 t; cvta.to.shared.u64 t, %1; cvt.u32.u64 %0, t; }"
        : "=r"(a) : "l"(p));
    return a;
}

__device__ __forceinline__ void mbar_init(uint32_t mbar, uint32_t cnt) {
    asm volatile("mbarrier.init.shared.b64 [%0], %1;" :: "r"(mbar), "r"(cnt) : "memory");
}
__device__ __forceinline__ void mbar_expect_tx(uint32_t mbar, uint32_t bytes) {
    asm volatile("mbarrier.arrive.expect_tx.shared.b64 _, [%0], %1;"
                 :: "r"(mbar), "r"(bytes) : "memory");
}
__device__ __forceinline__ void mbar_wait(uint32_t mbar, uint32_t parity) {
    asm volatile(
        "{\n\t"
        ".reg .pred P;\n\t"
        "WL_%=:\n\t"
        "mbarrier.try_wait.parity.acquire.cta.shared::cta.b64 P, [%0], %1, 0x989680;\n\t"
        "@P bra.uni WD_%=;\n\t"
        "bra.uni WL_%=;\n\t"
        "WD_%=:\n\t"
        "}"
        :: "r"(mbar), "r"(parity) : "memory");
}
__device__ __forceinline__ void bulk_load(uint32_t dst, const void* src,
                                          uint32_t bytes, uint32_t mbar) {
    asm volatile(
        "cp.async.bulk.shared::cta.global.mbarrier::complete_tx::bytes [%0], [%1], %2, [%3];"
        :: "r"(dst), "l"(src), "r"(bytes), "r"(mbar) : "memory");
}

__global__ __launch_bounds__(BLOCK) void dequant_kernel(
    const float4* __restrict__ codebooks,   // [512] float4
    const float*  __restrict__ scales,      // [NUMEL/64]
    const int*    __restrict__ codes,       // [NCODES]
    float4*       __restrict__ out4)        // [NCODES]
{
    __shared__ float4 s_cb[CB_ENTRIES];                         // 8 KB
    __shared__ __align__(128) float4 s_out[DEPTH][TILE_CODES];  // 2 x 16 KB
    __shared__ __align__(128) int    s_codes[DEPTH][TILE_CODES];// 2 x 4 KB
    __shared__ __align__(128) float  s_sc[DEPTH][SCALE_CNT];    // 2 x 256 B
    __shared__ __align__(8)  uint64_t s_mbar[DEPTH];

    const int t      = threadIdx.x;
    const int stride = gridDim.x;

    for (int i = t; i < CB_ENTRIES; i += BLOCK)
        s_cb[i] = codebooks[i];

    uint32_t mbar[DEPTH];
    #pragma unroll
    for (int d = 0; d < DEPTH; d++) mbar[d] = smem_u32(&s_mbar[d]);

    if (t == 0) {
        #pragma unroll
        for (int d = 0; d < DEPTH; d++) mbar_init(mbar[d], 1);
    }
    __syncthreads();   // mbarriers + codebook visible to all

    // Prologue: issue loads for the first DEPTH tiles.
    if (t == 0) {
        #pragma unroll
        for (int d = 0; d < DEPTH; d++) {
            long long tl = (long long)blockIdx.x + (long long)d * stride;
            if (tl < NTILES) {
                mbar_expect_tx(mbar[d], CODE_BYTES + SCALE_BYTES);
                bulk_load(smem_u32(&s_codes[d][0]), codes  + tl * TILE_CODES,
                          CODE_BYTES, mbar[d]);
                bulk_load(smem_u32(&s_sc[d][0]),    scales + tl * SCALE_CNT,
                          SCALE_BYTES, mbar[d]);
            }
        }
    }

    int ph0 = 0, ph1 = 0;   // per-buffer phase parity
    int iter = 0;
    for (int tile = blockIdx.x; tile < NTILES; tile += stride, iter++) {
        const int buf = iter & 1;

        // Wait for this buffer's codes/scales to land.
        if (buf == 0) { mbar_wait(mbar[0], ph0); ph0 ^= 1; }
        else          { mbar_wait(mbar[1], ph1); ph1 ^= 1; }

        // Ensure the bulk store issued 2 iterations ago has finished
        // reading s_out[buf] before we overwrite it.
        if (t == 0)
            asm volatile("cp.async.bulk.wait_group.read %0;" :: "n"(DEPTH - 1) : "memory");
        __syncthreads();

        const int cb_off = (tile >= (NTILES / 2)) ? 256 : 0;

        #pragma unroll
        for (int k = 0; k < CPT; k++) {
            const int idx = k * BLOCK + t;
            const int   c  = s_codes[buf][idx];
            const float sc = s_sc[buf][idx >> 4];
            float4 v = s_cb[cb_off + c];
            v.x *= sc; v.y *= sc; v.z *= sc; v.w *= sc;
            s_out[buf][idx] = v;
        }
        __syncthreads();

        if (t == 0) {
            // Stream this output tile to GMEM as one 16KB burst.
            asm volatile("fence.proxy.async.shared::cta;" ::: "memory");
            asm volatile(
                "cp.async.bulk.global.shared::cta.bulk_group [%0], [%1], %2;"
                :: "l"(out4 + (long long)tile * TILE_CODES),
                   "r"(smem_u32(&s_out[buf][0])), "n"(TILE_BYTES) : "memory");
            asm volatile("cp.async.bulk.commit_group;" ::: "memory");

            // Refill this codes buffer for tile + DEPTH*stride (codes were
            // consumed above; s_codes[buf] is free now).
            long long nt = (long long)tile + (long long)DEPTH * stride;
            if (nt < NTILES) {
                mbar_expect_tx(mbar[buf], CODE_BYTES + SCALE_BYTES);
                bulk_load(smem_u32(&s_codes[buf][0]), codes  + nt * TILE_CODES,
                          CODE_BYTES, mbar[buf]);
                bulk_load(smem_u32(&s_sc[buf][0]),    scales + nt * SCALE_CNT,
                          SCALE_BYTES, mbar[buf]);
            }
        }
    }

    // Drain outstanding bulk stores before exit.
    if (t == 0)
        asm volatile("cp.async.bulk.wait_group 0;" ::: "memory");
}

extern "C" void kernel_launch(void* const* d_in, const int* in_sizes, int n_in,
                              void* d_out, int out_size)
{
    // metadata order: codebooks [2,256,4] f32, scales [1M,1] f32, codes [2,8M] i32, rows, columns
    const float4* codebooks = (const float4*)d_in[0];
    const float*  scales    = (const float*)d_in[1];
    const int*    codes     = (const int*)d_in[2];
    float4*       out4      = (float4*)d_out;

    int grid = GRID;
    if (grid > NTILES) grid = NTILES;

    dequant_kernel<<<grid, BLOCK>>>(codebooks, scales, codes, out4);
}